// round 1
// baseline (speedup 1.0000x reference)
#include <cuda_runtime.h>

#define BB 8
#define CC 128
#define WW 4096
#define DD 16

// Scratch (allocation-free rule: __device__ globals)
__device__ float g_q[BB*WW*DD];      // [b][w][d]
__device__ float g_k[BB*WW*DD];      // [b][w][d]
__device__ float g_v[BB*CC*WW];      // [b][c][w]
__device__ float g_m[BB*WW];
__device__ float g_linv[BB*WW];

// Fast e^x for x <= ~1 (args are always <= 0 here). Pure FMA + bit trick,
// avoids MUFU (rt_SMSP=8 would bottleneck 134M exps at ~74/cyc chip-wide).
__device__ __forceinline__ float fexp(float x) {
    float y = fmaxf(x * 1.4426950408889634f, -126.0f);
    float r = rintf(y);
    float f = y - r;
    float p = 1.3333558146e-3f;
    p = fmaf(p, f, 9.6181291076e-3f);
    p = fmaf(p, f, 5.5504108665e-2f);
    p = fmaf(p, f, 2.4022650696e-1f);
    p = fmaf(p, f, 6.9314718056e-1f);
    p = fmaf(p, f, 1.0f);
    return __int_as_float(__float_as_int(p) + (((int)r) << 23));
}

// ---------------------------------------------------------------------------
// Kernel 1: fused projections q = Wq x + bq, k = Wk x + bk, v = Wv x + bv
// Block: one (b, 128-wide w tile). 256 threads. Dynamic smem 144KB.
// ---------------------------------------------------------------------------
__global__ void __launch_bounds__(256) k_proj(
    const float* __restrict__ x,
    const float* __restrict__ Wq, const float* __restrict__ bq,
    const float* __restrict__ Wk, const float* __restrict__ bk,
    const float* __restrict__ Wv, const float* __restrict__ bv)
{
    extern __shared__ float sm[];
    float* xs  = sm;                 // [C][128]   xs[c*128 + wl]
    float* wvs = sm + CC*128;        // [C][C]
    float* wqk = wvs + CC*CC;        // [2][D][C]
    const int b  = blockIdx.y;
    const int w0 = blockIdx.x * 128;
    const int tid = threadIdx.x;

    for (int i = tid; i < CC*128; i += 256) {
        int c = i >> 7, wl = i & 127;
        xs[i] = x[(b*CC + c)*WW + w0 + wl];
    }
    for (int i = tid; i < CC*CC; i += 256) wvs[i] = Wv[i];
    for (int i = tid; i < DD*CC; i += 256) { wqk[i] = Wq[i]; wqk[DD*CC + i] = Wk[i]; }
    __syncthreads();

    // ---- V projection as a 128x128 GEMM (K=128), 8x8 micro-tiles ----
    {
        const int o0  = (tid >> 4) * 8;
        const int twl = (tid & 15) * 8;
        float acc[8][8];
        #pragma unroll
        for (int oi = 0; oi < 8; oi++) {
            float bvv = bv[o0 + oi];
            #pragma unroll
            for (int wi = 0; wi < 8; wi++) acc[oi][wi] = bvv;
        }
        for (int c = 0; c < CC; c++) {
            float4 b0 = *(const float4*)&xs[c*128 + twl];
            float4 b1 = *(const float4*)&xs[c*128 + twl + 4];
            #pragma unroll
            for (int oi = 0; oi < 8; oi++) {
                float a = wvs[(o0 + oi)*CC + c];
                acc[oi][0] = fmaf(a, b0.x, acc[oi][0]);
                acc[oi][1] = fmaf(a, b0.y, acc[oi][1]);
                acc[oi][2] = fmaf(a, b0.z, acc[oi][2]);
                acc[oi][3] = fmaf(a, b0.w, acc[oi][3]);
                acc[oi][4] = fmaf(a, b1.x, acc[oi][4]);
                acc[oi][5] = fmaf(a, b1.y, acc[oi][5]);
                acc[oi][6] = fmaf(a, b1.z, acc[oi][6]);
                acc[oi][7] = fmaf(a, b1.w, acc[oi][7]);
            }
        }
        #pragma unroll
        for (int oi = 0; oi < 8; oi++) {
            float* op = &g_v[(b*CC + o0 + oi)*WW + w0 + twl];
            *(float4*)(op)     = make_float4(acc[oi][0], acc[oi][1], acc[oi][2], acc[oi][3]);
            *(float4*)(op + 4) = make_float4(acc[oi][4], acc[oi][5], acc[oi][6], acc[oi][7]);
        }
    }

    // ---- Q / K projections: threads [0,128) do q, [128,256) do k ----
    {
        const int wl   = tid & 127;
        const int half = tid >> 7;
        const float* Wm   = &wqk[half*DD*CC];
        const float* bias = half ? bk : bq;
        float acc[DD];
        #pragma unroll
        for (int d = 0; d < DD; d++) acc[d] = bias[d];
        for (int c = 0; c < CC; c++) {
            float xv = xs[c*128 + wl];
            #pragma unroll
            for (int d = 0; d < DD; d++) acc[d] = fmaf(Wm[d*CC + c], xv, acc[d]);
        }
        float* op = (half ? g_k : g_q) + (size_t)(b*WW + w0 + wl)*DD;
        #pragma unroll
        for (int d = 0; d < DD; d += 4)
            *(float4*)&op[d] = make_float4(acc[d], acc[d+1], acc[d+2], acc[d+3]);
    }
}

// ---------------------------------------------------------------------------
// Kernel 2: per-row softmax stats. m_j = max_w S[j,w], linv_j = 1/sum exp.
// Block: (b, 32 j-rows). 256 threads = 32 rows x 8 lanes. Online max/sum.
// ---------------------------------------------------------------------------
__global__ void __launch_bounds__(256) k_stats()
{
    __shared__ float ks[128*DD];
    const int b   = blockIdx.y;
    const int j0  = blockIdx.x * 32;
    const int tid = threadIdx.x;
    const int jl   = tid >> 3;
    const int lane = tid & 7;
    const int j = j0 + jl;

    const float4* qr = (const float4*)&g_q[(size_t)(b*WW + j)*DD];
    const float4 q0 = qr[0], q1 = qr[1], q2 = qr[2], q3 = qr[3];

    float m = -1e30f, l = 0.0f;

    for (int w0 = 0; w0 < WW; w0 += 128) {
        __syncthreads();
        for (int i = tid; i < 128*DD; i += 256)
            ks[i] = g_k[(size_t)(b*WW + w0)*DD + i];
        __syncthreads();
        #pragma unroll 4
        for (int ii = 0; ii < 16; ii++) {
            int wl = ii*8 + lane;
            const float4* kr = (const float4*)&ks[wl*DD];
            float4 k0 = kr[0], k1 = kr[1], k2 = kr[2], k3 = kr[3];
            float s = q0.x*k0.x + q0.y*k0.y + q0.z*k0.z + q0.w*k0.w
                    + q1.x*k1.x + q1.y*k1.y + q1.z*k1.z + q1.w*k1.w
                    + q2.x*k2.x + q2.y*k2.y + q2.z*k2.z + q2.w*k2.w
                    + q3.x*k3.x + q3.y*k3.y + q3.z*k3.z + q3.w*k3.w;
            s *= 0.25f;
            if (s <= m) {
                l += fexp(s - m);
            } else {
                l = fmaf(l, fexp(m - s), 1.0f);
                m = s;
            }
        }
    }
    // combine the 8 lanes of each row
    #pragma unroll
    for (int off = 4; off; off >>= 1) {
        float m2 = __shfl_down_sync(0xffffffffu, m, off, 8);
        float l2 = __shfl_down_sync(0xffffffffu, l, off, 8);
        float M = fmaxf(m, m2);
        l = l * fexp(m - M) + l2 * fexp(m2 - M);
        m = M;
    }
    if (lane == 0) {
        g_m[b*WW + j]    = m;
        g_linv[b*WW + j] = 1.0f / l;
    }
}

// ---------------------------------------------------------------------------
// Kernel 3: context[c,w] = sum_j v[c,j] * exp(S[j,w]-m_j)*linv_j, + residual.
// Block: (b, 64-wide w tile), 256 threads, full C=128 rows. Loop j in 32s:
// recompute S tile -> P tile in smem, then 4x8 register micro-tile GEMM.
// ---------------------------------------------------------------------------
__global__ void __launch_bounds__(256) k_ctx(const float* __restrict__ x,
                                             float* __restrict__ out)
{
    __shared__ float vs[CC*33];     // [c][jj], pad 33
    __shared__ float ps[32*68];     // [jj][wl], pad 68 (16B aligned rows)
    __shared__ float ksh[64*DD];
    __shared__ float qs[32*DD];
    __shared__ float msh[32], lsh[32];

    const int b   = blockIdx.y;
    const int wg0 = blockIdx.x * 64;
    const int tid = threadIdx.x;

    for (int i = tid; i < 64*DD; i += 256)
        ksh[i] = g_k[(size_t)(b*WW + wg0)*DD + i];

    float acc[4][8];
    #pragma unroll
    for (int ci = 0; ci < 4; ci++)
        #pragma unroll
        for (int wi = 0; wi < 8; wi++) acc[ci][wi] = 0.0f;

    const int tc = tid >> 3, tw = tid & 7;
    const int c0 = tc * 4, wl0 = tw * 8;

    for (int j0 = 0; j0 < WW; j0 += 32) {
        __syncthreads();
        for (int i = tid; i < CC*32; i += 256) {
            int c = i >> 5, jj = i & 31;
            vs[c*33 + jj] = g_v[(size_t)(b*CC + c)*WW + j0 + jj];
        }
        for (int i = tid; i < 32*DD; i += 256)
            qs[i] = g_q[(size_t)(b*WW + j0)*DD + i];
        if (tid < 32) {
            msh[tid] = g_m[b*WW + j0 + tid];
            lsh[tid] = g_linv[b*WW + j0 + tid];
        }
        __syncthreads();

        // P tile: 32 x 64
        for (int e = tid; e < 32*64; e += 256) {
            int j = e >> 6, wl = e & 63;
            const float4* qr = (const float4*)&qs[j*DD];
            const float4* kr = (const float4*)&ksh[wl*DD];
            float4 a0 = qr[0], a1 = qr[1], a2 = qr[2], a3 = qr[3];
            float4 b0 = kr[0], b1 = kr[1], b2 = kr[2], b3 = kr[3];
            float s = a0.x*b0.x + a0.y*b0.y + a0.z*b0.z + a0.w*b0.w
                    + a1.x*b1.x + a1.y*b1.y + a1.z*b1.z + a1.w*b1.w
                    + a2.x*b2.x + a2.y*b2.y + a2.z*b2.z + a2.w*b2.w
                    + a3.x*b3.x + a3.y*b3.y + a3.z*b3.z + a3.w*b3.w;
            ps[j*68 + wl] = fexp(fmaf(s, 0.25f, -msh[j])) * lsh[j];
        }
        __syncthreads();

        // accumulate: acc[ci][wi] += vs[c0+ci][jj] * ps[jj][wl0+wi]
        #pragma unroll 2
        for (int jj = 0; jj < 32; jj++) {
            float4 p0 = *(const float4*)&ps[jj*68 + wl0];
            float4 p1 = *(const float4*)&ps[jj*68 + wl0 + 4];
            #pragma unroll
            for (int ci = 0; ci < 4; ci++) {
                float a = vs[(c0 + ci)*33 + jj];
                acc[ci][0] = fmaf(a, p0.x, acc[ci][0]);
                acc[ci][1] = fmaf(a, p0.y, acc[ci][1]);
                acc[ci][2] = fmaf(a, p0.z, acc[ci][2]);
                acc[ci][3] = fmaf(a, p0.w, acc[ci][3]);
                acc[ci][4] = fmaf(a, p1.x, acc[ci][4]);
                acc[ci][5] = fmaf(a, p1.y, acc[ci][5]);
                acc[ci][6] = fmaf(a, p1.z, acc[ci][6]);
                acc[ci][7] = fmaf(a, p1.w, acc[ci][7]);
            }
        }
    }

    // epilogue: residual add + store
    #pragma unroll
    for (int ci = 0; ci < 4; ci++) {
        const float* xp = &x[(size_t)(b*CC + c0 + ci)*WW + wg0 + wl0];
        float*       op = &out[(size_t)(b*CC + c0 + ci)*WW + wg0 + wl0];
        float4 x0 = *(const float4*)xp;
        float4 x1 = *(const float4*)(xp + 4);
        *(float4*)op       = make_float4(acc[ci][0] + x0.x, acc[ci][1] + x0.y,
                                         acc[ci][2] + x0.z, acc[ci][3] + x0.w);
        *(float4*)(op + 4) = make_float4(acc[ci][4] + x1.x, acc[ci][5] + x1.y,
                                         acc[ci][6] + x1.z, acc[ci][7] + x1.w);
    }
}

// ---------------------------------------------------------------------------
extern "C" void kernel_launch(void* const* d_in, const int* in_sizes, int n_in,
                              void* d_out, int out_size)
{
    const float* x  = (const float*)d_in[0];
    const float* Wq = (const float*)d_in[1];
    const float* bq = (const float*)d_in[2];
    const float* Wk = (const float*)d_in[3];
    const float* bk = (const float*)d_in[4];
    const float* Wv = (const float*)d_in[5];
    const float* bv = (const float*)d_in[6];
    float* out = (float*)d_out;

    cudaFuncSetAttribute(k_proj, cudaFuncAttributeMaxDynamicSharedMemorySize, 147456);

    dim3 g1(WW/128, BB);
    k_proj<<<g1, 256, 147456>>>(x, Wq, bq, Wk, bk, Wv, bv);

    dim3 g2(WW/32, BB);
    k_stats<<<g2, 256>>>();

    dim3 g3(WW/64, BB);
    k_ctx<<<g3, 256>>>(x, out);
}